// round 11
// baseline (speedup 1.0000x reference)
#include <cuda_runtime.h>
#include <math.h>

// ---------------------------------------------------------------------------
// PolyNetFP4, ONE fused kernel (two kernels each pay a ~5.5us launch floor):
//   blocks 0..16  : in-place smem FP4 dequant + 257-node cubic (f, h*f') LUT
//                   -> g_lut -> atomicAdd(g_ready) -> exit
//   blocks 17..591: prefetch x float4 -> tight volatile poll on g_ready ->
//                   densify to 2048-interval linear (f, df) smem table ->
//                   grid-stride apply: 1 LDS.64 + 1 FMA per element.
// Flags self-reset (last block) -> graph-replay safe. No nanosleep (its
// wake-up slop was the fused-kernel killer in earlier rounds).
// ---------------------------------------------------------------------------

#define NCOARSE 256          // coarse cubic intervals (257 nodes)
#define NFINE   2048         // fine linear intervals (8 per coarse)
#define XMINF   (-16.0f)
#define HFC     0.125f       // coarse h, exact
#define INVHF   64.0f        // fine 1/h, exact
#define TOFFF   1024.0f      // -XMINF * INVHF
#define NB_BLK  17           // builder blocks (16 nodes each)
#define GRID    592          // 148 SMs * 4 CTAs
#define CONS    (GRID - NB_BLK)
#define TPB     512

__device__ float2 g_lut[NCOARSE + 1];   // (f(x_i), HFC * f'(x_i))
__device__ int    g_ready;              // builders-done counter (self-reset)
__device__ int    g_done;               // blocks-finished counter (self-reset)

// bitsandbytes FP4 code table, reference order (argmin -> first index on tie).
__constant__ float FP4C[16] = {
     0.0f,  0.0052083333f,  0.6666667f,  1.0f,  0.33333334f,  0.5f,
     0.16666667f,  0.25f,
    -0.0f, -0.0052083333f, -0.6666667f, -1.0f, -0.33333334f, -0.5f,
    -0.16666667f, -0.25f
};

__device__ __forceinline__ float sigfast(float z)
{
    return __fdividef(1.0f, 1.0f + __expf(-z));
}

// Shared arena float offsets (16B-aligned chunks).
// uS region is unioned: builder Phase-C scratch (16 warps x 256) OR the
// consumer fine linear table (2048 float2). Rows stride 66 (=264B: 8B-aligned
// float2 rows, conflict-free column reads).
#define U_SW2   0               // 64*66 = 4224
#define U_SW3   4224            // 32*66 = 2112
#define U_US    6336            // 4096
#define U_SW1   10432           // 64
#define U_SB1   10496           // 64
#define U_SB2   10560           // 64
#define U_SB3   10624           // 32
#define U_SW4   10656           // 32
#define U_SB4   10688           // 4
#define ARENA_N 10692           // 42.8 KB -> 4 CTAs/SM

__global__ __launch_bounds__(TPB, 4) void fused_kernel(
    const float* __restrict__ x, float* __restrict__ out, int n,
    const float* __restrict__ w1, const float* __restrict__ b1,
    const float* __restrict__ w2, const float* __restrict__ b2,
    const float* __restrict__ w3, const float* __restrict__ b3,
    const float* __restrict__ w4, const float* __restrict__ b4)
{
    __shared__ __align__(16) float arena[ARENA_N];
    float* const sw2p = arena + U_SW2;
    float* const sw3p = arena + U_SW3;
    float* const uS   = arena + U_US;
    float* const sw1  = arena + U_SW1;
    float* const sb1  = arena + U_SB1;
    float* const sb2  = arena + U_SB2;
    float* const sb3  = arena + U_SB3;
    float* const sw4s = arena + U_SW4;
    float* const sb4  = arena + U_SB4;

    const int tid = threadIdx.x;
    const int w   = tid >> 5, l = tid & 31;
    const int n4  = n >> 2;

    if (blockIdx.x < NB_BLK) {
        // =========================== BUILDER =================================
        // ---- Phase A: weights straight into their padded smem rows.
        {
            const float4* g2 = (const float4*)w2;   // 1024 float4
            #pragma unroll
            for (int t = tid; t < 1024; t += TPB) {
                float4 v = g2[t];
                int base = t << 2;
                float* d = sw2p + (base >> 6) * 66 + (base & 63);
                d[0] = v.x; d[1] = v.y; d[2] = v.z; d[3] = v.w;
            }
            const float4* g3 = (const float4*)w3;   // 512 float4
            {
                float4 v = g3[tid];
                int base = tid << 2;
                float* d = sw3p + (base >> 6) * 66 + (base & 63);
                d[0] = v.x; d[1] = v.y; d[2] = v.z; d[3] = v.w;
            }
            if (tid < 64) { sw1[tid] = w1[tid]; sb1[tid] = b1[tid]; sb2[tid] = b2[tid]; }
            if (tid < 32) { sw4s[tid] = w4[tid]; sb3[tid] = b3[tid]; }
            if (tid == 0) sb4[0] = b4[0];
        }
        __syncthreads();

        // ---- Phase B: FP4 roundtrip IN PLACE (quant block == smem row).
        for (int task = w; task < 98; task += 16) {
            float* row;
            int    cnt = 64;
            if (task == 0)       row = sw1;
            else if (task <= 64) row = sw2p + (task - 1) * 66;
            else if (task <= 96) row = sw3p + (task - 65) * 66;
            else               { row = sw4s; cnt = 32; }

            float v0 = row[l];
            float v1 = (l + 32 < cnt) ? row[l + 32] : 0.0f;
            float am = fmaxf(fabsf(v0), fabsf(v1));
            #pragma unroll
            for (int off = 16; off; off >>= 1)
                am = fmaxf(am, __shfl_xor_sync(0xffffffffu, am, off));

            float scale = (am == 0.0f) ? 1.0f : am;

            #pragma unroll
            for (int r = 0; r < 2; r++) {
                int   i = l + 32 * r;
                float v = r ? v1 : v0;
                if (i < cnt) {
                    float s    = v / scale;      // IEEE div: matches jnp
                    int   best = 0;
                    float bd   = fabsf(s - FP4C[0]);
                    #pragma unroll
                    for (int c = 1; c < 16; c++) {
                        float d = fabsf(s - FP4C[c]);
                        if (d < bd) { bd = d; best = c; }   // first-min = argmin
                    }
                    row[i] = FP4C[best] * am;
                }
            }
        }
        __syncthreads();

        // ---- Phase C: one node per warp; forward-mode derivative.
        int node = blockIdx.x * 16 + w;
        if (node <= NCOARSE) {
            float  xv = fmaf((float)node, HFC, XMINF);
            float* sh = uS + w * 256;  // h1[0:64] d1[64:128] h2[128:192] d2[192:256]

            #pragma unroll
            for (int r = 0; r < 2; r++) {
                int   j = l + 32 * r;
                float z = fmaf(sw1[j], xv, sb1[j]);
                float s = sigfast(z);
                sh[j]      = z * s;
                sh[64 + j] = (s + z * s * (1.0f - s)) * sw1[j];
            }
            __syncwarp();

            {
                float acc0 = sb2[l],      dacc0 = 0.0f;
                float acc1 = sb2[l + 32], dacc1 = 0.0f;
                const float2* row0 = (const float2*)&sw2p[l * 66];
                const float2* row1 = (const float2*)&sw2p[(l + 32) * 66];
                const float2* hv   = (const float2*)&sh[0];
                const float2* dv   = (const float2*)&sh[64];
                #pragma unroll
                for (int j2 = 0; j2 < 32; j2++) {
                    float2 h  = hv[j2];
                    float2 d  = dv[j2];
                    float2 wa = row0[j2];
                    float2 wb = row1[j2];
                    acc0  = fmaf(wa.x, h.x, fmaf(wa.y, h.y, acc0));
                    dacc0 = fmaf(wa.x, d.x, fmaf(wa.y, d.y, dacc0));
                    acc1  = fmaf(wb.x, h.x, fmaf(wb.y, h.y, acc1));
                    dacc1 = fmaf(wb.x, d.x, fmaf(wb.y, d.y, dacc1));
                }
                float s0 = sigfast(acc0);
                float s1 = sigfast(acc1);
                sh[128 + l]      = acc0 * s0;
                sh[192 + l]      = (s0 + acc0 * s0 * (1.0f - s0)) * dacc0;
                sh[128 + l + 32] = acc1 * s1;
                sh[192 + l + 32] = (s1 + acc1 * s1 * (1.0f - s1)) * dacc1;
            }
            __syncwarp();

            {
                float acc = sb3[l], dacc = 0.0f;
                const float2* row = (const float2*)&sw3p[l * 66];
                const float2* hv  = (const float2*)&sh[128];
                const float2* dv  = (const float2*)&sh[192];
                #pragma unroll
                for (int j2 = 0; j2 < 32; j2++) {
                    float2 h  = hv[j2];
                    float2 d  = dv[j2];
                    float2 wv = row[j2];
                    acc  = fmaf(wv.x, h.x, fmaf(wv.y, h.y, acc));
                    dacc = fmaf(wv.x, d.x, fmaf(wv.y, d.y, dacc));
                }
                float s  = sigfast(acc);
                float h3 = acc * s;
                float d3 = (s + acc * s * (1.0f - s)) * dacc;

                float p  = sw4s[l] * h3;
                float dp = sw4s[l] * d3;
                #pragma unroll
                for (int off = 16; off; off >>= 1) {
                    p  += __shfl_xor_sync(0xffffffffu, p,  off);
                    dp += __shfl_xor_sync(0xffffffffu, dp, off);
                }
                if (l == 0)
                    g_lut[node] = make_float2(p + sb4[0], HFC * dp);
            }
        }
        __syncthreads();
        if (tid == 0) {
            __threadfence();               // publish g_lut before the flag
            atomicAdd(&g_ready, 1);
        }
    } else {
        // =========================== CONSUMER ================================
        const int gtid = (blockIdx.x - NB_BLK) * TPB + tid;
        const int cstr = CONS * TPB;
        const float4* x4 = (const float4*)x;
        float4*       o4 = (float4*)out;

        // Prefetch the first float4 while builders run.
        float4 v0;
        const bool has0 = (gtid < n4);
        if (has0) v0 = x4[gtid];

        // Tight read-only poll (NO nanosleep: its wake-up slop sets the tail).
        if (tid == 0) {
            while (*(volatile int*)&g_ready < NB_BLK) { }
            __threadfence();               // acquire
        }
        __syncthreads();

        // Densify: fine entries [4t, 4t+4), all inside coarse c = t >> 1.
        float2* slin = (float2*)uS;
        {
            int    c  = tid >> 1;
            float2 A  = __ldcg(&g_lut[c]);
            float2 B  = __ldcg(&g_lut[c + 1]);
            float dlt = B.x - A.x;
            float c2  = 3.0f * dlt - 2.0f * A.y - B.y;
            float c3  = A.y + B.y - 2.0f * dlt;
            float u0  = (tid & 1) ? 0.5f : 0.0f;
            float vprev = fmaf(u0, fmaf(u0, fmaf(u0, c3, c2), A.y), A.x);
            #pragma unroll
            for (int k = 1; k <= 4; k++) {
                float uu = u0 + (float)k * 0.125f;
                float vk = fmaf(uu, fmaf(uu, fmaf(uu, c3, c2), A.y), A.x);
                slin[tid * 4 + k - 1] = make_float2(vprev, vk - vprev);
                vprev = vk;
            }
        }
        __syncthreads();

        #define EV1(xe, dst) {                              \
            float t_ = fmaf((xe), INVHF, TOFFF);            \
            t_ = fminf(fmaxf(t_, 0.0f), 2047.999f);         \
            int   i_ = (int)t_;                             \
            float u_ = t_ - (float)i_;                      \
            float2 c_ = slin[i_];                           \
            (dst) = fmaf(u_, c_.y, c_.x);                   \
        }

        if (has0) {
            float4 r;
            EV1(v0.x, r.x); EV1(v0.y, r.y); EV1(v0.z, r.z); EV1(v0.w, r.w);
            o4[gtid] = r;
        }
        for (int i = gtid + cstr; i < n4; i += cstr) {
            float4 v = x4[i];
            float4 r;
            EV1(v.x, r.x); EV1(v.y, r.y); EV1(v.z, r.z); EV1(v.w, r.w);
            o4[i] = r;
        }
        for (int i = n4 * 4 + gtid; i < n; i += cstr)
        {
            float r;
            EV1(x[i], r);
            out[i] = r;
        }
        #undef EV1
        __syncthreads();
    }

    // ---- Self-reset for the next graph replay (last finishing block).
    if (tid == 0) {
        int k = atomicAdd(&g_done, 1);
        if (k == GRID - 1) {
            atomicExch(&g_done, 0);
            atomicExch(&g_ready, 0);
        }
    }
}

// ---------------------------------------------------------------------------
extern "C" void kernel_launch(void* const* d_in, const int* in_sizes, int n_in,
                              void* d_out, int out_size)
{
    const float* x  = (const float*)d_in[0];
    const float* w1 = (const float*)d_in[1];
    const float* b1 = (const float*)d_in[2];
    const float* w2 = (const float*)d_in[3];
    const float* b2 = (const float*)d_in[4];
    const float* w3 = (const float*)d_in[5];
    const float* b3 = (const float*)d_in[6];
    const float* w4 = (const float*)d_in[7];
    const float* b4 = (const float*)d_in[8];
    int n = in_sizes[0];

    fused_kernel<<<GRID, TPB>>>(x, (float*)d_out, n,
                                w1, b1, w2, b2, w3, b3, w4, b4);
}